// round 9
// baseline (speedup 1.0000x reference)
#include <cuda_runtime.h>
#include <math.h>

#define Bq 4
#define Lq 4096
#define Hq 8
#define Dq 64
#define SK 9
#define U  9
#define BH (Bq*Hq)
#define NCH 16
#define CHK (Lq/NCH)    // 256
#define TCH 8
#define TCHK (Lq/TCH)   // 512

// scratch (static __device__ arrays — zero-initialized, no allocation)
__device__ float  g_M[BH * Lq];
__device__ int    g_top[BH * U];
__device__ float4 g_vmean4[BH * (Dq/4)];
__device__ float  g_cand_v[BH * TCH * U];
__device__ int    g_cand_i[BH * TCH * U];
__device__ int    g_cnt[BH];
__device__ int    g_cnt2[BH];
__device__ float  g_scores[BH * U * Lq];          // raw (scaled) scores
__device__ float  g_cmax[BH * NCH * U];           // per-chunk row max
__device__ float  g_csum[BH * NCH * U];           // per-chunk row sum(exp(s-m_c))
__device__ float  g_part[BH * NCH * 10 * Dq];     // per-chunk: 9 ctx rows + vsum
__device__ float  g_ctxtop[BH * U * Dq];

// ---------------------------------------------------------------------------
// L0: sampled scores. One warp per (b,l) covering ALL 8 heads.
// ---------------------------------------------------------------------------
__global__ void __launch_bounds__(128)
k_sample(const float* __restrict__ q,
         const float* __restrict__ k,
         const int*   __restrict__ idx)
{
    int warp = (blockIdx.x * 128 + threadIdx.x) >> 5;   // 0..Bq*Lq-1
    int lane = threadIdx.x & 31;
    int l = warp & (Lq - 1);
    int b = warp >> 12;

    const float4* qrow = (const float4*)(q + (size_t)(b * Lq + l) * Hq * Dq);
    float4 q4[4];
#pragma unroll
    for (int r = 0; r < 4; r++) q4[r] = qrow[lane + 32 * r];

    int ks[SK];
#pragma unroll
    for (int s = 0; s < SK; s++) ks[s] = idx[l * SK + s];

    int half = lane >> 4;
    int rsel = lane & 15;        // lanes with rsel<4 track head 2*rsel+half

    float mx = -INFINITY, sm = 0.f;
#pragma unroll
    for (int g3 = 0; g3 < SK; g3 += 3) {
        float4 kv[3][4];
#pragma unroll
        for (int j = 0; j < 3; j++) {
            const float4* krow = (const float4*)(k + (size_t)(b * Lq + ks[g3 + j]) * Hq * Dq);
#pragma unroll
            for (int r = 0; r < 4; r++) kv[j][r] = krow[lane + 32 * r];
        }
#pragma unroll
        for (int j = 0; j < 3; j++) {
#pragma unroll
            for (int r = 0; r < 4; r++) {
                float p = kv[j][r].x * q4[r].x + kv[j][r].y * q4[r].y
                        + kv[j][r].z * q4[r].z + kv[j][r].w * q4[r].w;
                p += __shfl_xor_sync(0xffffffffu, p, 1);
                p += __shfl_xor_sync(0xffffffffu, p, 2);
                p += __shfl_xor_sync(0xffffffffu, p, 4);
                p += __shfl_xor_sync(0xffffffffu, p, 8);
                if (rsel == r) { mx = fmaxf(mx, p); sm += p; }
            }
        }
    }

    if (rsel < 4) {
        int h = 2 * rsel + half;
        g_M[(b * Hq + h) * Lq + l] = mx - sm * (1.0f / (float)Lq);
    }
}

// ---------------------------------------------------------------------------
// L1: per-chunk top-9; last finishing block per bh merges candidates
// grid = bh*TCH, 128 threads
// ---------------------------------------------------------------------------
__global__ void __launch_bounds__(128)
k_topk()
{
    int blk = blockIdx.x;
    int bh = blk >> 3, ch = blk & 7;
    int base = ch * TCHK;
    int t = threadIdx.x;

    __shared__ float sv[TCHK];
    __shared__ float rv[128];
    __shared__ int   ri[128];

    for (int i = t; i < TCHK; i += 128) sv[i] = g_M[bh * Lq + base + i];
    __syncthreads();

    for (int r = 0; r < U; r++) {
        float bv = -INFINITY; int bi = 0x7fffffff;
#pragma unroll
        for (int j = 0; j < TCHK / 128; j++) {
            int i = t + j * 128;
            float vv = sv[i];
            if (vv > bv || (vv == bv && i < bi)) { bv = vv; bi = i; }
        }
        rv[t] = bv; ri[t] = bi;
        __syncthreads();
        for (int o = 64; o > 0; o >>= 1) {
            if (t < o) {
                float v2 = rv[t + o]; int i2 = ri[t + o];
                if (v2 > rv[t] || (v2 == rv[t] && i2 < ri[t])) { rv[t] = v2; ri[t] = i2; }
            }
            __syncthreads();
        }
        if (t == 0) {
            g_cand_v[blk * U + r] = rv[0];
            g_cand_i[blk * U + r] = base + ri[0];
            sv[ri[0]] = -INFINITY;
        }
        __syncthreads();
    }

    __threadfence();
    __shared__ int is_last;
    if (t == 0) is_last = (atomicAdd(&g_cnt[bh], 1) == TCH - 1);
    __syncthreads();
    if (!is_last || t >= 32) return;
    if (t == 0) g_cnt[bh] = 0;           // reset for next graph replay

    const int NC = TCH * U;          // 72
    float v0 = -INFINITY, v1 = -INFINITY, v2 = -INFINITY;
    int   i0 = 0x7fffffff, i1 = 0x7fffffff, i2 = 0x7fffffff;
    if (t      < NC) { v0 = g_cand_v[bh * NC + t];      i0 = g_cand_i[bh * NC + t]; }
    if (t + 32 < NC) { v1 = g_cand_v[bh * NC + t + 32]; i1 = g_cand_i[bh * NC + t + 32]; }
    if (t + 64 < NC) { v2 = g_cand_v[bh * NC + t + 64]; i2 = g_cand_i[bh * NC + t + 64]; }

    for (int r = 0; r < U; r++) {
        float bv = v0; int bi = i0;
        if (v1 > bv || (v1 == bv && i1 < bi)) { bv = v1; bi = i1; }
        if (v2 > bv || (v2 == bv && i2 < bi)) { bv = v2; bi = i2; }
#pragma unroll
        for (int o = 16; o > 0; o >>= 1) {
            float ov = __shfl_xor_sync(0xffffffffu, bv, o);
            int   oi = __shfl_xor_sync(0xffffffffu, bi, o);
            if (ov > bv || (ov == bv && oi < bi)) { bv = ov; bi = oi; }
        }
        if (t == 0) g_top[bh * U + r] = bi;
        if (i0 == bi) v0 = -INFINITY;
        if (i1 == bi) v1 = -INFINITY;
        if (i2 == bi) v2 = -INFINITY;
    }
}

// ---------------------------------------------------------------------------
// L2: raw scores + per-chunk softmax stats; grid = bh*NCH (512), 256 threads
// one key per thread; 2 syncthreads total for the stats
// ---------------------------------------------------------------------------
__global__ void __launch_bounds__(256)
k_scores(const float* __restrict__ q, const float* __restrict__ k)
{
    int blk = blockIdx.x;
    int bh = blk >> 4, ch = blk & 15;
    int b = bh / Hq, h = bh % Hq;
    int t = threadIdx.x;
    int wid = t >> 5, lane = t & 31;

    __shared__ float qr[U * Dq];
    __shared__ float redm[8][U];
    __shared__ float rede[8][U];
    for (int i = t; i < U * Dq; i += 256) {
        int r = i >> 6, d = i & 63;
        int l = g_top[bh * U + r];
        qr[i] = q[((size_t)(b * Lq + l) * Hq + h) * Dq + d];
    }
    __syncthreads();

    const float scale = 0.125f;
    int kk = ch * CHK + t;
    const float4* krow = (const float4*)(k + ((size_t)(b * Lq + kk) * Hq + h) * Dq);
    float s[U];
#pragma unroll
    for (int r = 0; r < U; r++) s[r] = 0.f;
#pragma unroll
    for (int i = 0; i < Dq / 4; i++) {
        float4 kv = krow[i];
#pragma unroll
        for (int r = 0; r < U; r++) {
            s[r] += kv.x * qr[r * Dq + 4 * i + 0]
                  + kv.y * qr[r * Dq + 4 * i + 1]
                  + kv.z * qr[r * Dq + 4 * i + 2]
                  + kv.w * qr[r * Dq + 4 * i + 3];
        }
    }
#pragma unroll
    for (int r = 0; r < U; r++) {
        s[r] *= scale;
        g_scores[((size_t)(bh * U + r)) * Lq + kk] = s[r];
    }

    // batched chunk max (1 sync)
#pragma unroll
    for (int r = 0; r < U; r++) {
        float m = s[r];
#pragma unroll
        for (int o = 16; o > 0; o >>= 1) m = fmaxf(m, __shfl_xor_sync(0xffffffffu, m, o));
        if (lane == 0) redm[wid][r] = m;
    }
    __syncthreads();
    float m_c[U];
#pragma unroll
    for (int r = 0; r < U; r++) {
        float m = redm[0][r];
#pragma unroll
        for (int j = 1; j < 8; j++) m = fmaxf(m, redm[j][r]);
        m_c[r] = m;
    }

    // batched chunk sum(exp) (1 sync)
#pragma unroll
    for (int r = 0; r < U; r++) {
        float e = expf(s[r] - m_c[r]);
#pragma unroll
        for (int o = 16; o > 0; o >>= 1) e += __shfl_xor_sync(0xffffffffu, e, o);
        if (lane == 0) rede[wid][r] = e;
    }
    __syncthreads();
    if (t < U) {
        float S = 0.f;
#pragma unroll
        for (int j = 0; j < 8; j++) S += rede[j][t];
        g_cmax[blk * U + t] = m_c[t];
        g_csum[blk * U + t] = S;
    }
}

// ---------------------------------------------------------------------------
// L3 (profiled): attn write + ctx partials + V sum; grid = bh*NCH (512), 256 thr
// ---------------------------------------------------------------------------
__global__ void __launch_bounds__(256)
k_attn_ctx(const float* __restrict__ v, float* __restrict__ out)
{
    int blk = blockIdx.x;
    int bh = blk >> 4, ch = blk & 15;
    int b = bh / Hq, h = bh % Hq;
    int t = threadIdx.x;

    __shared__ float sa[U * CHK];          // normalized attn for this chunk
    __shared__ float sm_m[U], sm_is[U];
    __shared__ float cred[4 * 10 * Dq];

    if (t < U) {
        float m_r = -INFINITY;
#pragma unroll
        for (int c = 0; c < NCH; c++) m_r = fmaxf(m_r, g_cmax[(bh * NCH + c) * U + t]);
        float S = 0.f;
#pragma unroll
        for (int c = 0; c < NCH; c++)
            S += g_csum[(bh * NCH + c) * U + t] * expf(g_cmax[(bh * NCH + c) * U + t] - m_r);
        sm_m[t] = m_r;
        sm_is[t] = 1.0f / S;
    }
    __syncthreads();

    // pass 1: coalesced attn computation + write
    float* attn = out + (size_t)Bq * Lq * Hq * Dq + (size_t)bh * U * Lq;
    int base = ch * CHK;
#pragma unroll
    for (int i = t; i < U * CHK; i += 256) {
        int r = i >> 8, j = i & (CHK - 1);
        float s = g_scores[((size_t)(bh * U + r)) * Lq + base + j];
        float a = expf(s - sm_m[r]) * sm_is[r];
        sa[i] = a;
        attn[(size_t)r * Lq + base + j] = a;
    }
    __syncthreads();

    // pass 2: ctx partials + V sum (single V read)
    {
        int d = t & 63, g = t >> 6;       // 4 k-groups x 64 d
        float acc[U];
        float accv = 0.f;
#pragma unroll
        for (int r = 0; r < U; r++) acc[r] = 0.f;
        for (int j = g; j < CHK; j += 4) {
            float vv = v[((size_t)(b * Lq + base + j) * Hq + h) * Dq + d];
            accv += vv;
#pragma unroll
            for (int r = 0; r < U; r++) acc[r] += sa[(r << 8) + j] * vv;
        }
#pragma unroll
        for (int r = 0; r < U; r++) cred[((g * 10 + r) << 6) + d] = acc[r];
        cred[((g * 10 + 9) << 6) + d] = accv;
    }
    __syncthreads();

    for (int i = t; i < 10 * Dq; i += 256) {
        int row = i >> 6, dd = i & 63;
        float s = 0.f;
#pragma unroll
        for (int gg = 0; gg < 4; gg++) s += cred[((gg * 10 + row) << 6) + dd];
        g_part[((size_t)(bh * NCH + ch) * 10 + row) * Dq + dd] = s;
    }

    // last block of this bh: final reduce -> ctx_top + vmean
    __threadfence();
    __shared__ int is_last;
    if (t == 0) is_last = (atomicAdd(&g_cnt2[bh], 1) == NCH - 1);
    __syncthreads();
    if (!is_last) return;
    if (t == 0) g_cnt2[bh] = 0;          // reset for next graph replay

    for (int i = t; i < 10 * Dq; i += 256) {
        int row = i >> 6, dd = i & 63;
        float s = 0.f;
#pragma unroll
        for (int c = 0; c < NCH; c++)
            s += g_part[((size_t)(bh * NCH + c) * 10 + row) * Dq + dd];
        if (row < U) g_ctxtop[(bh * U + row) * Dq + dd] = s;
        else ((float*)g_vmean4)[bh * Dq + dd] = s * (1.0f / (float)Lq);
    }
}

// ---------------------------------------------------------------------------
// L4: final context write: vmean everywhere, ctx_top at top rows
// ---------------------------------------------------------------------------
#define NBCAST ((Bq*Lq*Hq*Dq/4)/256)   // 8192

__global__ void __launch_bounds__(256)
k_bcast(float4* __restrict__ out4)
{
    int f = blockIdx.x * 256 + threadIdx.x;
    int b = f >> 19;
    int h = (f >> 4) & 7;
    int l = (f >> 7) & 4095;
    int bh = b * Hq + h;
    int rr = -1;
#pragma unroll
    for (int r = 0; r < U; r++) if (g_top[bh * U + r] == l) rr = r;
    float4 val;
    if (rr >= 0) val = ((const float4*)g_ctxtop)[(bh * U + rr) * 16 + (f & 15)];
    else         val = g_vmean4[(bh << 4) + (f & 15)];
    out4[f] = val;
}

// ---------------------------------------------------------------------------
extern "C" void kernel_launch(void* const* d_in, const int* in_sizes, int n_in,
                              void* d_out, int out_size)
{
    const float* q   = (const float*)d_in[0];
    const float* k   = (const float*)d_in[1];
    const float* v   = (const float*)d_in[2];
    const int*   idx = (const int*)d_in[3];
    float* out = (float*)d_out;

    (void)in_sizes; (void)n_in; (void)out_size;

    k_sample<<<(Bq * Lq) / 4, 128>>>(q, k, idx);      // 0
    k_topk<<<BH * TCH, 128>>>();                      // 1
    k_scores<<<BH * NCH, 256>>>(q, k);                // 2
    k_attn_ctx<<<BH * NCH, 256>>>(v, out);            // 3  <- profiled slot
    k_bcast<<<NBCAST, 256>>>((float4*)out);           // 4
}

// round 10
// speedup vs baseline: 1.2070x; 1.2070x over previous
#include <cuda_runtime.h>
#include <math.h>

#define Bq 4
#define Lq 4096
#define Hq 8
#define Dq 64
#define SK 9
#define U  9
#define BH (Bq*Hq)
#define NCH 8
#define CHK (Lq/NCH)    // 512
#define PITCH 513       // padded score-tile row pitch (conflict-free)

// scratch (static __device__ arrays — zero-initialized, no allocation)
__device__ float  g_M[BH * Lq];
__device__ int    g_top[BH * U];
__device__ float4 g_vmean4[BH * (Dq/4)];
__device__ float  g_cand_v[BH * NCH * U];
__device__ int    g_cand_i[BH * NCH * U];
__device__ int    g_cnt[BH];
__device__ int    g_cnt2[BH];
__device__ float  g_scores[BH * U * Lq];          // scaled scores
__device__ float  g_cmax[BH * NCH * U];
__device__ float  g_csum[BH * NCH * U];
__device__ float  g_part[BH * NCH * 10 * Dq];     // 9 ctx rows + vsum
__device__ float  g_ctxtop[BH * U * Dq];

// ---------------------------------------------------------------------------
// L0: sampled scores. One warp per (b,l) covering ALL 8 heads.
// ---------------------------------------------------------------------------
__global__ void __launch_bounds__(128)
k_sample(const float* __restrict__ q,
         const float* __restrict__ k,
         const int*   __restrict__ idx)
{
    int warp = (blockIdx.x * 128 + threadIdx.x) >> 5;
    int lane = threadIdx.x & 31;
    int l = warp & (Lq - 1);
    int b = warp >> 12;

    const float4* qrow = (const float4*)(q + (size_t)(b * Lq + l) * Hq * Dq);
    float4 q4[4];
#pragma unroll
    for (int r = 0; r < 4; r++) q4[r] = qrow[lane + 32 * r];

    int ks[SK];
#pragma unroll
    for (int s = 0; s < SK; s++) ks[s] = idx[l * SK + s];

    int half = lane >> 4;
    int rsel = lane & 15;

    float mx = -INFINITY, sm = 0.f;
#pragma unroll
    for (int g3 = 0; g3 < SK; g3 += 3) {
        float4 kv[3][4];
#pragma unroll
        for (int j = 0; j < 3; j++) {
            const float4* krow = (const float4*)(k + (size_t)(b * Lq + ks[g3 + j]) * Hq * Dq);
#pragma unroll
            for (int r = 0; r < 4; r++) kv[j][r] = krow[lane + 32 * r];
        }
#pragma unroll
        for (int j = 0; j < 3; j++) {
#pragma unroll
            for (int r = 0; r < 4; r++) {
                float p = kv[j][r].x * q4[r].x + kv[j][r].y * q4[r].y
                        + kv[j][r].z * q4[r].z + kv[j][r].w * q4[r].w;
                p += __shfl_xor_sync(0xffffffffu, p, 1);
                p += __shfl_xor_sync(0xffffffffu, p, 2);
                p += __shfl_xor_sync(0xffffffffu, p, 4);
                p += __shfl_xor_sync(0xffffffffu, p, 8);
                if (rsel == r) { mx = fmaxf(mx, p); sm += p; }
            }
        }
    }

    if (rsel < 4) {
        int h = 2 * rsel + half;
        g_M[(b * Hq + h) * Lq + l] = mx - sm * (1.0f / (float)Lq);
    }
}

// ---------------------------------------------------------------------------
// L1: per-chunk top-9; last finishing block per bh merges candidates
// ---------------------------------------------------------------------------
__global__ void __launch_bounds__(128)
k_topk()
{
    int blk = blockIdx.x;
    int bh = blk >> 3, ch = blk & 7;
    int base = ch * CHK;
    int t = threadIdx.x;

    __shared__ float sv[CHK];
    __shared__ float rv[128];
    __shared__ int   ri[128];

    for (int i = t; i < CHK; i += 128) sv[i] = g_M[bh * Lq + base + i];
    __syncthreads();

    for (int r = 0; r < U; r++) {
        float bv = -INFINITY; int bi = 0x7fffffff;
#pragma unroll
        for (int j = 0; j < CHK / 128; j++) {
            int i = t + j * 128;
            float vv = sv[i];
            if (vv > bv || (vv == bv && i < bi)) { bv = vv; bi = i; }
        }
        rv[t] = bv; ri[t] = bi;
        __syncthreads();
        for (int o = 64; o > 0; o >>= 1) {
            if (t < o) {
                float v2 = rv[t + o]; int i2 = ri[t + o];
                if (v2 > rv[t] || (v2 == rv[t] && i2 < ri[t])) { rv[t] = v2; ri[t] = i2; }
            }
            __syncthreads();
        }
        if (t == 0) {
            g_cand_v[blk * U + r] = rv[0];
            g_cand_i[blk * U + r] = base + ri[0];
            sv[ri[0]] = -INFINITY;
        }
        __syncthreads();
    }

    __threadfence();
    __shared__ int is_last;
    if (t == 0) is_last = (atomicAdd(&g_cnt[bh], 1) == NCH - 1);
    __syncthreads();
    if (!is_last || t >= 32) return;
    if (t == 0) g_cnt[bh] = 0;

    const int NC = NCH * U;          // 72
    float v0 = -INFINITY, v1 = -INFINITY, v2 = -INFINITY;
    int   i0 = 0x7fffffff, i1 = 0x7fffffff, i2 = 0x7fffffff;
    if (t      < NC) { v0 = g_cand_v[bh * NC + t];      i0 = g_cand_i[bh * NC + t]; }
    if (t + 32 < NC) { v1 = g_cand_v[bh * NC + t + 32]; i1 = g_cand_i[bh * NC + t + 32]; }
    if (t + 64 < NC) { v2 = g_cand_v[bh * NC + t + 64]; i2 = g_cand_i[bh * NC + t + 64]; }

    for (int r = 0; r < U; r++) {
        float bv = v0; int bi = i0;
        if (v1 > bv || (v1 == bv && i1 < bi)) { bv = v1; bi = i1; }
        if (v2 > bv || (v2 == bv && i2 < bi)) { bv = v2; bi = i2; }
#pragma unroll
        for (int o = 16; o > 0; o >>= 1) {
            float ov = __shfl_xor_sync(0xffffffffu, bv, o);
            int   oi = __shfl_xor_sync(0xffffffffu, bi, o);
            if (ov > bv || (ov == bv && oi < bi)) { bv = ov; bi = oi; }
        }
        if (t == 0) g_top[bh * U + r] = bi;
        if (i0 == bi) v0 = -INFINITY;
        if (i1 == bi) v1 = -INFINITY;
        if (i2 == bi) v2 = -INFINITY;
    }
}

// ---------------------------------------------------------------------------
// L2: scores v2 — half-warp per key (coalesced K), smem-staged, 2-sync stats
// grid = bh*NCH (256), 256 threads (8 warps, 64 keys/warp)
// ---------------------------------------------------------------------------
__global__ void __launch_bounds__(256)
k_scores(const float* __restrict__ q, const float* __restrict__ k)
{
    int blk = blockIdx.x;
    int bh = blk >> 3, ch = blk & 7;
    int b = bh / Hq, h = bh % Hq;
    int t = threadIdx.x;
    int w = t >> 5, lane = t & 31;
    int half = lane >> 4, rsel = lane & 15;

    __shared__ float qr[U * Dq];
    __shared__ float s_tile[U * PITCH];
    __shared__ float redm[8][U];
    __shared__ float rede[8][U];

    // stage scaled Q_reduce rows
    for (int i = t; i < U * Dq; i += 256) {
        int r = i >> 6, d = i & 63;
        int l = g_top[bh * U + r];
        qr[i] = q[((size_t)(b * Lq + l) * Hq + h) * Dq + d] * 0.125f;
    }
    __syncthreads();

    // per-lane Q registers (float4 slice of each row)
    float4 qreg[U];
#pragma unroll
    for (int r = 0; r < U; r++)
        qreg[r] = ((const float4*)qr)[r * 16 + rsel];

    int base = ch * CHK;

    // phase A: 32 key-pairs per warp, half-warp per key
    for (int iter = 0; iter < 32; iter++) {
        int klocal = w * 64 + 2 * iter + half;
        int kk = base + klocal;
        const float4* krow = (const float4*)(k + ((size_t)(b * Lq + kk) * Hq + h) * Dq);
        float4 kv = krow[rsel];
        float dot[U];
#pragma unroll
        for (int r = 0; r < U; r++)
            dot[r] = kv.x * qreg[r].x + kv.y * qreg[r].y
                   + kv.z * qreg[r].z + kv.w * qreg[r].w;
#pragma unroll
        for (int o = 1; o <= 8; o <<= 1) {
#pragma unroll
            for (int r = 0; r < U; r++)
                dot[r] += __shfl_xor_sync(0xffffffffu, dot[r], o);
        }
        float vsel = dot[0];
        if (rsel == 1) vsel = dot[1];
        if (rsel == 2) vsel = dot[2];
        if (rsel == 3) vsel = dot[3];
        if (rsel == 4) vsel = dot[4];
        if (rsel == 5) vsel = dot[5];
        if (rsel == 6) vsel = dot[6];
        if (rsel == 7) vsel = dot[7];
        if (rsel == 8) vsel = dot[8];
        if (rsel < U) s_tile[rsel * PITCH + klocal] = vsel;
    }
    __syncthreads();

    // phase B: coalesced write + chunk stats (2 keys/thread)
    float s0[U], s1[U];
#pragma unroll
    for (int r = 0; r < U; r++) {
        s0[r] = s_tile[r * PITCH + t];
        s1[r] = s_tile[r * PITCH + t + 256];
        g_scores[((size_t)(bh * U + r)) * Lq + base + t]       = s0[r];
        g_scores[((size_t)(bh * U + r)) * Lq + base + t + 256] = s1[r];
    }

#pragma unroll
    for (int r = 0; r < U; r++) {
        float m = fmaxf(s0[r], s1[r]);
#pragma unroll
        for (int o = 16; o > 0; o >>= 1) m = fmaxf(m, __shfl_xor_sync(0xffffffffu, m, o));
        if (lane == 0) redm[w][r] = m;
    }
    __syncthreads();
    float m_c[U];
#pragma unroll
    for (int r = 0; r < U; r++) {
        float m = redm[0][r];
#pragma unroll
        for (int j = 1; j < 8; j++) m = fmaxf(m, redm[j][r]);
        m_c[r] = m;
    }
#pragma unroll
    for (int r = 0; r < U; r++) {
        float e = expf(s0[r] - m_c[r]) + expf(s1[r] - m_c[r]);
#pragma unroll
        for (int o = 16; o > 0; o >>= 1) e += __shfl_xor_sync(0xffffffffu, e, o);
        if (lane == 0) rede[w][r] = e;
    }
    __syncthreads();
    if (t < U) {
        float S = 0.f;
#pragma unroll
        for (int j = 0; j < 8; j++) S += rede[j][t];
        g_cmax[blk * U + t] = m_c[t];
        g_csum[blk * U + t] = S;
    }
}

// ---------------------------------------------------------------------------
// L3 (profiled): attn write + ctx partials + V sum; grid = bh*NCH (256), 512 thr
// float4 V loads, 32 rows in flight, shfl pair-reduce + smem cred.
// dynamic smem: sa[U*CHK] | cred[16*10*Dq]
// ---------------------------------------------------------------------------
#define ACTX_SMEM ((U*CHK + 16*10*Dq) * sizeof(float))

__global__ void __launch_bounds__(512)
k_attn_ctx(const float* __restrict__ v, float* __restrict__ out)
{
    extern __shared__ float smem[];
    float* sa   = smem;                  // U*CHK = 4608
    float* cred = sa + U * CHK;          // 16*10*64 = 10240

    int blk = blockIdx.x;
    int bh = blk >> 3, ch = blk & 7;
    int b = bh / Hq, h = bh % Hq;
    int t = threadIdx.x;

    __shared__ float sm_m[U], sm_is[U];

    if (t < U) {
        float m_r = -INFINITY;
#pragma unroll
        for (int c = 0; c < NCH; c++) m_r = fmaxf(m_r, g_cmax[(bh * NCH + c) * U + t]);
        float S = 0.f;
#pragma unroll
        for (int c = 0; c < NCH; c++)
            S += g_csum[(bh * NCH + c) * U + t] * expf(g_cmax[(bh * NCH + c) * U + t] - m_r);
        sm_m[t] = m_r;
        sm_is[t] = 1.0f / S;
    }
    __syncthreads();

    // pass 1: attn computation + write
    float* attn = out + (size_t)Bq * Lq * Hq * Dq + (size_t)bh * U * Lq;
    int base = ch * CHK;
#pragma unroll
    for (int i = t; i < U * CHK; i += 512) {
        int r = i >> 9, j = i & (CHK - 1);
        float s = g_scores[((size_t)(bh * U + r)) * Lq + base + j];
        float a = expf(s - sm_m[r]) * sm_is[r];
        sa[i] = a;
        attn[(size_t)r * Lq + base + j] = a;
    }
    __syncthreads();

    // pass 2: ctx partials + V sum, float4
    {
        int d4 = t & 15;                 // which float4 of the row
        int rg = t >> 4;                 // 32 row-groups
        float4 acc[U];
        float4 accv = make_float4(0.f, 0.f, 0.f, 0.f);
#pragma unroll
        for (int r = 0; r < U; r++) acc[r] = make_float4(0.f, 0.f, 0.f, 0.f);

        for (int j = rg; j < CHK; j += 32) {
            const float4* vrow = (const float4*)(v + ((size_t)(b * Lq + base + j) * Hq + h) * Dq);
            float4 vv = vrow[d4];
            accv.x += vv.x; accv.y += vv.y; accv.z += vv.z; accv.w += vv.w;
#pragma unroll
            for (int r = 0; r < U; r++) {
                float a = sa[(r << 9) + j];
                acc[r].x += a * vv.x; acc[r].y += a * vv.y;
                acc[r].z += a * vv.z; acc[r].w += a * vv.w;
            }
        }

        // reduce row-group pairs within warp (lanes L and L^16 share d4)
#pragma unroll
        for (int r = 0; r < U; r++) {
            acc[r].x += __shfl_xor_sync(0xffffffffu, acc[r].x, 16);
            acc[r].y += __shfl_xor_sync(0xffffffffu, acc[r].y, 16);
            acc[r].z += __shfl_xor_sync(0xffffffffu, acc[r].z, 16);
            acc[r].w += __shfl_xor_sync(0xffffffffu, acc[r].w, 16);
        }
        accv.x += __shfl_xor_sync(0xffffffffu, accv.x, 16);
        accv.y += __shfl_xor_sync(0xffffffffu, accv.y, 16);
        accv.z += __shfl_xor_sync(0xffffffffu, accv.z, 16);
        accv.w += __shfl_xor_sync(0xffffffffu, accv.w, 16);

        int w = t >> 5;
        if ((t & 31) < 16) {
#pragma unroll
            for (int r = 0; r < U; r++)
                ((float4*)cred)[(w * 10 + r) * 16 + d4] = acc[r];
            ((float4*)cred)[(w * 10 + 9) * 16 + d4] = accv;
        }
    }
    __syncthreads();

    for (int i = t; i < 10 * Dq; i += 512) {
        int row = i >> 6, dd = i & 63;
        float s = 0.f;
#pragma unroll
        for (int w = 0; w < 16; w++) s += cred[(w * 10 + row) * Dq + dd];
        g_part[((size_t)(bh * NCH + ch) * 10 + row) * Dq + dd] = s;
    }

    __threadfence();
    __shared__ int is_last;
    if (t == 0) is_last = (atomicAdd(&g_cnt2[bh], 1) == NCH - 1);
    __syncthreads();
    if (!is_last) return;
    if (t == 0) g_cnt2[bh] = 0;

    for (int i = t; i < 10 * Dq; i += 512) {
        int row = i >> 6, dd = i & 63;
        float s = 0.f;
#pragma unroll
        for (int c = 0; c < NCH; c++)
            s += g_part[((size_t)(bh * NCH + c) * 10 + row) * Dq + dd];
        if (row < U) g_ctxtop[(bh * U + row) * Dq + dd] = s;
        else ((float*)g_vmean4)[bh * Dq + dd] = s * (1.0f / (float)Lq);
    }
}

// ---------------------------------------------------------------------------
// L4: final context write: vmean everywhere, ctx_top at top rows
// ---------------------------------------------------------------------------
#define NBCAST ((Bq*Lq*Hq*Dq/4)/256)   // 8192

__global__ void __launch_bounds__(256)
k_bcast(float4* __restrict__ out4)
{
    int f = blockIdx.x * 256 + threadIdx.x;
    int b = f >> 19;
    int h = (f >> 4) & 7;
    int l = (f >> 7) & 4095;
    int bh = b * Hq + h;
    int rr = -1;
#pragma unroll
    for (int r = 0; r < U; r++) if (g_top[bh * U + r] == l) rr = r;
    float4 val;
    if (rr >= 0) val = ((const float4*)g_ctxtop)[(bh * U + rr) * 16 + (f & 15)];
    else         val = g_vmean4[(bh << 4) + (f & 15)];
    out4[f] = val;
}

// ---------------------------------------------------------------------------
extern "C" void kernel_launch(void* const* d_in, const int* in_sizes, int n_in,
                              void* d_out, int out_size)
{
    const float* q   = (const float*)d_in[0];
    const float* k   = (const float*)d_in[1];
    const float* v   = (const float*)d_in[2];
    const int*   idx = (const int*)d_in[3];
    float* out = (float*)d_out;

    (void)in_sizes; (void)n_in; (void)out_size;

    static int attr_set = 0;
    if (!attr_set) {
        cudaFuncSetAttribute(k_attn_ctx, cudaFuncAttributeMaxDynamicSharedMemorySize,
                             (int)ACTX_SMEM);
        attr_set = 1;
    }

    k_sample<<<(Bq * Lq) / 4, 128>>>(q, k, idx);          // 0
    k_topk<<<BH * NCH, 128>>>();                          // 1
    k_scores<<<BH * NCH, 256>>>(q, k);                    // 2
    k_attn_ctx<<<BH * NCH, 512, ACTX_SMEM>>>(v, out);     // 3  <- profiled slot
    k_bcast<<<NBCAST, 256>>>((float4*)out);               // 4
}